// round 16
// baseline (speedup 1.0000x reference)
#include <cuda_runtime.h>
#include <cstdint>

#define Bb 4
#define Mm 256
#define Tt 64
#define BT 256      // B*T
#define KD 512      // 2M == D_MOT == D_ABS
#define DOUT 768
#define NF4 (DOUT/4)   // 192 float4 per row
#define JSPLIT 8       // stage1 j-split (32 j-rows per plane) -> grid 512
#define KSPLIT 8       // stage2 A-row k-split (64 k per plane); base rows use 2 (256 k)
#define PSZ (3*BT*KD)  // S buffer (768 x 512)

// Accumulation arena. Invariant at kernel_launch entry: S region is ZERO
// (true at module load; re-established by epilogue each run). S2+cv are
// zeroed by stage1 (which runs before stage2 writes them). RED.ADD everywhere.
#define OFF_S  0
#define OFF_S2 (PSZ)
#define OFF_CV (PSZ + 1024*DOUT)
#define TOTF   (PSZ + 1024*DOUT + DOUT)
#define S2CV_F4 ((1024*DOUT + DOUT)/4)   // float4 count of S2+cv region
__device__ float d_acc[TOTF];

__device__ __forceinline__ bool is_nan_bits(float x) {
    return (__float_as_uint(x) & 0x7fffffffu) > 0x7f800000u;
}

// ---------------------------------------------------------------------------
// stage1 (inline V, RED.ADD out): tile 64bt x 32k x 32j, microtile 4bt x 2k.
//   S0 += V@We, S1 += V@Wo, SU += VX@We + VY@Wo
// Also zeroes S2+cv region (distributed over the 512 blocks, overlapped).
// grid=(4 bt-tiles x64, 16 k-tiles x32, JSPLIT=8), block=256.
// ---------------------------------------------------------------------------
__global__ void stage1_kernel(const float* __restrict__ coords,
                              const float* __restrict__ vis,
                              const float* __restrict__ fc1w) {
    __shared__ float Vt [16][64], VXt[16][64], VYt[16][64];
    __shared__ float W0t[16][32], W1t[16][32];
    int b   = blockIdx.x;          // batch == bt-tile
    int bt0 = b * 64;
    int k0  = blockIdx.y * 32;
    int jb  = blockIdx.z * 32;     // 32 j-rows per split plane
    int t  = threadIdx.x;
    int tx = t & 15;       // k pair  (k = k0 + tx*2)
    int ty = t >> 4;       // bt quad (bt = bt0 + ty*4)

    // ---- distributed zero of S2+cv (512 blocks x 256 threads) ----
    {
        int bid = (blockIdx.z*16 + blockIdx.y)*4 + blockIdx.x;  // 0..511
        float4* z = (float4*)(d_acc + OFF_S2);
        const int per = (S2CV_F4 + 512*256 - 1) / (512*256);    // 2
        int base = (bid*256 + t)*per;
        #pragma unroll
        for (int q = 0; q < per; q++) {
            int idx = base + q;
            if (idx < S2CV_F4) z[idx] = make_float4(0.f,0.f,0.f,0.f);
        }
    }

    float s0[4][2], s1[4][2], su[4][2];
    #pragma unroll
    for (int i = 0; i < 4; i++)
        #pragma unroll
        for (int j = 0; j < 2; j++) { s0[i][j]=0.f; s1[i][j]=0.f; su[i][j]=0.f; }

    int lj  = t >> 4;          // V load row 0..15
    int lc  = (t & 15) * 4;    // V load col quad
    int ljw = t >> 3;          // W load row 0..15 (t<128)
    int lcw = (t & 7) * 4;     // W load col quad

    float4 c01, c23, vv4, rw0, rw1;
    {
        int jrow = jb + lj;
        int cbase = (b*Mm + jrow)*Tt + lc;
        c01 = *(const float4*)&coords[2*cbase];
        c23 = *(const float4*)&coords[2*cbase + 4];
        vv4 = *(const float4*)&vis[cbase];
        if (t < 128) {
            int jw = jb + ljw;
            rw0 = *(const float4*)&fc1w[(2*jw  )*KD + k0 + lcw];
            rw1 = *(const float4*)&fc1w[(2*jw+1)*KD + k0 + lcw];
        }
    }

    for (int jc = 0; jc < 32; jc += 16) {
        {   // convert + store to smem
            float xs[4] = {c01.x, c01.z, c23.x, c23.z};
            float ys[4] = {c01.y, c01.w, c23.y, c23.w};
            float vs[4] = {vv4.x, vv4.y, vv4.z, vv4.w};
            #pragma unroll
            for (int e = 0; e < 4; e++) {
                if (is_nan_bits(xs[e])) { vs[e] = 0.f; xs[e] = 0.f; }
                if (is_nan_bits(ys[e])) { ys[e] = 0.f; }
            }
            *(float4*)&Vt [lj][lc] = make_float4(vs[0], vs[1], vs[2], vs[3]);
            *(float4*)&VXt[lj][lc] = make_float4(xs[0]*vs[0], xs[1]*vs[1], xs[2]*vs[2], xs[3]*vs[3]);
            *(float4*)&VYt[lj][lc] = make_float4(ys[0]*vs[0], ys[1]*vs[1], ys[2]*vs[2], ys[3]*vs[3]);
            if (t < 128) {
                *(float4*)&W0t[ljw][lcw] = rw0;
                *(float4*)&W1t[ljw][lcw] = rw1;
            }
        }
        __syncthreads();
        if (jc + 16 < 32) {            // prefetch next chunk (hidden by FMA)
            int jrow = jb + jc + 16 + lj;
            int cbase = (b*Mm + jrow)*Tt + lc;
            c01 = *(const float4*)&coords[2*cbase];
            c23 = *(const float4*)&coords[2*cbase + 4];
            vv4 = *(const float4*)&vis[cbase];
            if (t < 128) {
                int jw = jb + jc + 16 + ljw;
                rw0 = *(const float4*)&fc1w[(2*jw  )*KD + k0 + lcw];
                rw1 = *(const float4*)&fc1w[(2*jw+1)*KD + k0 + lcw];
            }
        }
        #pragma unroll
        for (int kk = 0; kk < 16; kk++) {
            float4 v4 = *(const float4*)&Vt [kk][ty*4];
            float4 x4 = *(const float4*)&VXt[kk][ty*4];
            float4 y4 = *(const float4*)&VYt[kk][ty*4];
            float2 w0 = *(const float2*)&W0t[kk][tx*2];
            float2 w1 = *(const float2*)&W1t[kk][tx*2];
            float vv[4] = {v4.x,v4.y,v4.z,v4.w};
            float xx[4] = {x4.x,x4.y,x4.z,x4.w};
            float yy[4] = {y4.x,y4.y,y4.z,y4.w};
            float a0[2] = {w0.x,w0.y};
            float a1[2] = {w1.x,w1.y};
            #pragma unroll
            for (int i = 0; i < 4; i++)
                #pragma unroll
                for (int j = 0; j < 2; j++) {
                    s0[i][j] = fmaf(vv[i], a0[j], s0[i][j]);
                    s1[i][j] = fmaf(vv[i], a1[j], s1[i][j]);
                    su[i][j] = fmaf(xx[i], a0[j], fmaf(yy[i], a1[j], su[i][j]));
                }
        }
        __syncthreads();
    }
    // RED.ADD into the single S plane
    float* S = d_acc + OFF_S;
    #pragma unroll
    for (int i = 0; i < 4; i++) {
        int bt = bt0 + ty*4 + i;
        int k  = k0 + tx*2;
        #pragma unroll
        for (int j = 0; j < 2; j++) {
            atomicAdd(&S[(0*BT + bt)*KD + k + j], s0[i][j]);
            atomicAdd(&S[(1*BT + bt)*KD + k + j], s1[i][j]);
            atomicAdd(&S[(2*BT + bt)*KD + k + j], su[i][j]);
        }
    }
}

// ---------------------------------------------------------------------------
// stage2 (RED.ADD output, fused cvec): C (1024 x 768), K = 512.
//   A rows   (by 0..11):  A = S,   B = W2_top, split-K=8 (64 k/plane)
//   base rows(by 12..15): A = pos, B = W2_bot, split-K=2 (256 k, bz<2)
// by==0 blocks accumulate cvec = fc1b @ W2_top slice into d_acc cvec.
// grid=(12, 16, 8), block=128, microtile 8x4, reg-prefetch pipeline.
// ---------------------------------------------------------------------------
__global__ void stage2_kernel(const float* __restrict__ fcoutw,
                              const float* __restrict__ pos,
                              const float* __restrict__ fc1b,
                              const float* __restrict__ fcoutb) {
    __shared__ float At[16][64];
    __shared__ float Bt[16][64];
    __shared__ float fb[16];
    int bx = blockIdx.x;           // n tile
    int by = blockIdx.y;           // m tile
    int bz = blockIdx.z;           // k split
    bool isBase = (by >= 12);
    if (isBase && bz >= 2) return;            // base rows only in planes 0,1
    bool doCvec = (by == 0);
    const float* Ap = isBase ? (pos + (by-12)*64*KD) : (d_acc + OFF_S + by*64*KD);
    const float* Bp = fcoutw + (isBase ? KD*DOUT : 0) + bx*64;
    int t  = threadIdx.x;
    int tx = t & 15;    // 4 cols
    int ty = t >> 4;    // 8 rows
    float acc[8][4];
    #pragma unroll
    for (int i = 0; i < 8; i++)
        #pragma unroll
        for (int j = 0; j < 4; j++) acc[i][j] = 0.f;
    float accC[4] = {0.f, 0.f, 0.f, 0.f};

    int arow = t >> 1;          // 0..63
    int koff = (t & 1) * 8;
    int bk   = t >> 4;          // 0..7 (and +8)
    int bn   = (t & 15) * 4;

    int kbeg = isBase ? bz*256 : bz*64;
    int kend = kbeg + (isBase ? 256 : 64);
    float4 ra0, ra1, rb0, rb1;
    ra0 = *(const float4*)&Ap[arow*KD + kbeg + koff];
    ra1 = *(const float4*)&Ap[arow*KD + kbeg + koff + 4];
    rb0 = *(const float4*)&Bp[(kbeg+bk  )*DOUT + bn];
    rb1 = *(const float4*)&Bp[(kbeg+bk+8)*DOUT + bn];

    for (int kc = kbeg; kc < kend; kc += 16) {
        At[koff+0][arow] = ra0.x; At[koff+1][arow] = ra0.y;
        At[koff+2][arow] = ra0.z; At[koff+3][arow] = ra0.w;
        At[koff+4][arow] = ra1.x; At[koff+5][arow] = ra1.y;
        At[koff+6][arow] = ra1.z; At[koff+7][arow] = ra1.w;
        *(float4*)&Bt[bk  ][bn] = rb0;
        *(float4*)&Bt[bk+8][bn] = rb1;
        if (doCvec && t < 16) fb[t] = fc1b[kc + t];
        __syncthreads();
        if (kc + 16 < kend) {            // prefetch next chunk
            ra0 = *(const float4*)&Ap[arow*KD + kc + 16 + koff];
            ra1 = *(const float4*)&Ap[arow*KD + kc + 16 + koff + 4];
            rb0 = *(const float4*)&Bp[(kc+16+bk  )*DOUT + bn];
            rb1 = *(const float4*)&Bp[(kc+16+bk+8)*DOUT + bn];
        }
        #pragma unroll
        for (int kk = 0; kk < 16; kk++) {
            float4 b4 = *(const float4*)&Bt[kk][tx*4];
            float4 aA = *(const float4*)&At[kk][ty*8];
            float4 aB = *(const float4*)&At[kk][ty*8 + 4];
            float av[8] = {aA.x,aA.y,aA.z,aA.w,aB.x,aB.y,aB.z,aB.w};
            float bv[4] = {b4.x,b4.y,b4.z,b4.w};
            if (doCvec) {
                float fbv = fb[kk];
                #pragma unroll
                for (int j = 0; j < 4; j++)
                    accC[j] = fmaf(fbv, bv[j], accC[j]);
            }
            #pragma unroll
            for (int i = 0; i < 8; i++)
                #pragma unroll
                for (int j = 0; j < 4; j++)
                    acc[i][j] = fmaf(av[i], bv[j], acc[i][j]);
        }
        __syncthreads();
    }

    int row0 = by*64 + ty*8;
    int col  = bx*64 + tx*4;
    if (doCvec && ty == 0) {
        if (bz == 0) {
            accC[0] += fcoutb[col];   accC[1] += fcoutb[col+1];
            accC[2] += fcoutb[col+2]; accC[3] += fcoutb[col+3];
        }
        float* cvp = d_acc + OFF_CV;
        #pragma unroll
        for (int j = 0; j < 4; j++)
            atomicAdd(&cvp[col + j], accC[j]);
    }
    float* S2 = d_acc + OFF_S2;
    #pragma unroll
    for (int i = 0; i < 8; i++)
        #pragma unroll
        for (int j = 0; j < 4; j++)
            atomicAdd(&S2[(row0+i)*DOUT + col + j], acc[i][j]);
}

// ---------------------------------------------------------------------------
// epilogue: out[bt,m,o] = VX*A0 + VY*A1 - V*AU + base[m,o] + cvec[o]
// Single-plane reads. 384 threads: warps 0-5 -> bt {0,1}, warps 6-11 -> bt
// {2,3}. Base tile (16 m, +cvec) in 49 KB smem; A in regs; simple store loop.
// Tail: zero the S region for the NEXT replay (distributed).
// grid=(64 bt-quads, 16 m-tiles).
// ---------------------------------------------------------------------------
#define EPI_BT 4
#define EPI_M  16
#define EPI_THREADS 384
__global__ __launch_bounds__(EPI_THREADS, 3)
void epilogue_kernel(const float* __restrict__ coords,
                     const float* __restrict__ vis,
                     float* __restrict__ out) {
    extern __shared__ float4 sm[];
    float4* sBase = sm;                    // [EPI_M][192]
    float4* sVp   = sm + EPI_M*NF4;        // [EPI_M][EPI_BT] (vx, vy, v, 0)

    int bt0 = blockIdx.x * EPI_BT;
    int m0  = blockIdx.y * EPI_M;
    int t   = threadIdx.x;     // 0..383
    int w   = t >> 5, l = t & 31;
    int tcol = (w % 6)*32 + l;   // 0..191
    int bth  = w / 6;            // 0 or 1 (bt half)

    const float4* S2 = (const float4*)(d_acc + OFF_S2);

    float4 cv = ((const float4*)(d_acc + OFF_CV))[tcol];

    #pragma unroll
    for (int k = 0; k < EPI_M/2; k++) {
        int mm = bth*(EPI_M/2) + k;
        float4 u = S2[(768 + m0 + mm)*NF4 + tcol];
        sBase[mm*NF4 + tcol] = make_float4(u.x+cv.x, u.y+cv.y, u.z+cv.z, u.w+cv.w);
    }
    float4 a0[2], a1[2], au[2];
    #pragma unroll
    for (int i = 0; i < 2; i++) {
        int bt = bt0 + bth*2 + i;
        a0[i] = S2[(0*BT + bt)*NF4 + tcol];
        a1[i] = S2[(1*BT + bt)*NF4 + tcol];
        au[i] = S2[(2*BT + bt)*NF4 + tcol];
    }
    if (t < EPI_M*EPI_BT) {
        int mm = t >> 2, bi = t & 3;
        int bt = bt0 + bi;
        int b = bt >> 6, tt = bt & 63;
        int ci = (b*Mm + (m0+mm))*Tt + tt;
        float x = coords[2*ci], y = coords[2*ci+1], v = vis[ci];
        if (is_nan_bits(x)) { v = 0.f; x = 0.f; }
        if (is_nan_bits(y)) { y = 0.f; }
        sVp[mm*EPI_BT + bi] = make_float4(x*v, y*v, v, 0.f);
    }

    // distributed zero of S region for next replay (1024 blocks x 384 thr)
    {
        int bid = blockIdx.y*64 + blockIdx.x;               // 0..1023
        float4* z = (float4*)(d_acc + OFF_S);
        int idx = bid*384 + t;
        const int SF4 = PSZ/4;                              // 98304
        if (idx < SF4) z[idx] = make_float4(0.f,0.f,0.f,0.f);
    }
    __syncthreads();

    #pragma unroll 4
    for (int mm = 0; mm < EPI_M; mm++) {
        float4 bv = sBase[mm*NF4 + tcol];
        int m = m0 + mm;
        #pragma unroll
        for (int i = 0; i < 2; i++) {
            float4 vp = sVp[mm*EPI_BT + bth*2 + i];
            float4 o4;
            o4.x = fmaf(vp.x, a0[i].x, fmaf(vp.y, a1[i].x, fmaf(-vp.z, au[i].x, bv.x)));
            o4.y = fmaf(vp.x, a0[i].y, fmaf(vp.y, a1[i].y, fmaf(-vp.z, au[i].y, bv.y)));
            o4.z = fmaf(vp.x, a0[i].z, fmaf(vp.y, a1[i].z, fmaf(-vp.z, au[i].z, bv.z)));
            o4.w = fmaf(vp.x, a0[i].w, fmaf(vp.y, a1[i].w, fmaf(-vp.z, au[i].w, bv.w)));
            ((float4*)out)[((bt0 + bth*2 + i)*Mm + m)*NF4 + tcol] = o4;
        }
    }
}

// ---------------------------------------------------------------------------
extern "C" void kernel_launch(void* const* d_in, const int* in_sizes, int n_in,
                              void* d_out, int out_size) {
    const float* coords = (const float*)d_in[0];
    const float* vis    = (const float*)d_in[1];
    const float* pos    = (const float*)d_in[2];
    const float* fc1w   = (const float*)d_in[3];
    const float* fc1b   = (const float*)d_in[4];
    const float* fcoutw = (const float*)d_in[5];
    const float* fcoutb = (const float*)d_in[6];
    float* out = (float*)d_out;

    static int smem_set = 0;
    int epi_smem = EPI_M*NF4*16 + EPI_M*EPI_BT*16;   // 50,176 B
    if (!smem_set) {
        cudaFuncSetAttribute(epilogue_kernel,
                             cudaFuncAttributeMaxDynamicSharedMemorySize, epi_smem);
        smem_set = 1;
    }

    stage1_kernel  <<<dim3(4,16,JSPLIT), 256>>>(coords, vis, fc1w);
    stage2_kernel  <<<dim3(12,16,KSPLIT), 128>>>(fcoutw, pos, fc1b, fcoutb);
    epilogue_kernel<<<dim3(BT/EPI_BT, Mm/EPI_M), EPI_THREADS, epi_smem>>>(coords, vis, out);
}

// round 17
// speedup vs baseline: 1.0365x; 1.0365x over previous
#include <cuda_runtime.h>
#include <cstdint>

#define Bb 4
#define Mm 256
#define Tt 64
#define BT 256      // B*T
#define KD 512      // 2M == D_MOT == D_ABS
#define DOUT 768
#define NF4 (DOUT/4)   // 192 float4 per row
#define JSPLIT 4       // stage1 j-split (64 j-rows per plane)  [R15 best]
#define KSPLIT 8       // stage2 A-row k-split (64 k per plane); base rows use 2 (256 k)
#define PSZ (3*BT*KD)  // S buffer (768 x 512)

// Accumulation arena. Invariant at kernel_launch entry: S region is ZERO
// (true at module load; re-established by epilogue each run). S2+cv are
// zeroed by stage1; all stage2 accesses to them are post-gridsync.
#define OFF_S  0
#define OFF_S2 (PSZ)
#define OFF_CV (PSZ + 1024*DOUT)
#define TOTF   (PSZ + 1024*DOUT + DOUT)
#define S2CV_F4 ((1024*DOUT + DOUT)/4)   // float4 count of S2+cv region
__device__ float d_acc[TOTF];

__device__ __forceinline__ bool is_nan_bits(float x) {
    return (__float_as_uint(x) & 0x7fffffffu) > 0x7f800000u;
}

// ---------------------------------------------------------------------------
// stage1 (inline V, RED.ADD out): tile 64bt x 32k x 64j, microtile 4bt x 2k.
// Triggers programmatic launch completion at top so stage2's independent
// (base-row) blocks can run concurrently on leftover SM capacity.
// grid=(4 bt-tiles x64, 16 k-tiles x32, JSPLIT=4), block=256.
// ---------------------------------------------------------------------------
__global__ void stage1_kernel(const float* __restrict__ coords,
                              const float* __restrict__ vis,
                              const float* __restrict__ fc1w) {
#if __CUDA_ARCH__ >= 900
    cudaTriggerProgrammaticLaunchCompletion();
#endif
    __shared__ float Vt [16][64], VXt[16][64], VYt[16][64];
    __shared__ float W0t[16][32], W1t[16][32];
    int b   = blockIdx.x;          // batch == bt-tile
    int bt0 = b * 64;
    int k0  = blockIdx.y * 32;
    int jb  = blockIdx.z * 64;     // 64 j-rows per split plane
    int t  = threadIdx.x;
    int tx = t & 15;       // k pair  (k = k0 + tx*2)
    int ty = t >> 4;       // bt quad (bt = bt0 + ty*4)

    // ---- distributed zero of S2+cv (256 blocks x 256 threads) ----
    {
        int bid = (blockIdx.z*16 + blockIdx.y)*4 + blockIdx.x;  // 0..255
        float4* z = (float4*)(d_acc + OFF_S2);
        const int per = (S2CV_F4 + 256*256 - 1) / (256*256);    // 3
        int base = (bid*256 + t)*per;
        #pragma unroll
        for (int q = 0; q < per; q++) {
            int idx = base + q;
            if (idx < S2CV_F4) z[idx] = make_float4(0.f,0.f,0.f,0.f);
        }
    }

    float s0[4][2], s1[4][2], su[4][2];
    #pragma unroll
    for (int i = 0; i < 4; i++)
        #pragma unroll
        for (int j = 0; j < 2; j++) { s0[i][j]=0.f; s1[i][j]=0.f; su[i][j]=0.f; }

    int lj  = t >> 4;          // V load row 0..15
    int lc  = (t & 15) * 4;    // V load col quad
    int ljw = t >> 3;          // W load row 0..15 (t<128)
    int lcw = (t & 7) * 4;     // W load col quad

    float4 c01, c23, vv4, rw0, rw1;
    {
        int jrow = jb + lj;
        int cbase = (b*Mm + jrow)*Tt + lc;
        c01 = *(const float4*)&coords[2*cbase];
        c23 = *(const float4*)&coords[2*cbase + 4];
        vv4 = *(const float4*)&vis[cbase];
        if (t < 128) {
            int jw = jb + ljw;
            rw0 = *(const float4*)&fc1w[(2*jw  )*KD + k0 + lcw];
            rw1 = *(const float4*)&fc1w[(2*jw+1)*KD + k0 + lcw];
        }
    }

    for (int jc = 0; jc < 64; jc += 16) {
        {   // convert + store to smem
            float xs[4] = {c01.x, c01.z, c23.x, c23.z};
            float ys[4] = {c01.y, c01.w, c23.y, c23.w};
            float vs[4] = {vv4.x, vv4.y, vv4.z, vv4.w};
            #pragma unroll
            for (int e = 0; e < 4; e++) {
                if (is_nan_bits(xs[e])) { vs[e] = 0.f; xs[e] = 0.f; }
                if (is_nan_bits(ys[e])) { ys[e] = 0.f; }
            }
            *(float4*)&Vt [lj][lc] = make_float4(vs[0], vs[1], vs[2], vs[3]);
            *(float4*)&VXt[lj][lc] = make_float4(xs[0]*vs[0], xs[1]*vs[1], xs[2]*vs[2], xs[3]*vs[3]);
            *(float4*)&VYt[lj][lc] = make_float4(ys[0]*vs[0], ys[1]*vs[1], ys[2]*vs[2], ys[3]*vs[3]);
            if (t < 128) {
                *(float4*)&W0t[ljw][lcw] = rw0;
                *(float4*)&W1t[ljw][lcw] = rw1;
            }
        }
        __syncthreads();
        if (jc + 16 < 64) {            // prefetch next chunk (hidden by FMA)
            int jrow = jb + jc + 16 + lj;
            int cbase = (b*Mm + jrow)*Tt + lc;
            c01 = *(const float4*)&coords[2*cbase];
            c23 = *(const float4*)&coords[2*cbase + 4];
            vv4 = *(const float4*)&vis[cbase];
            if (t < 128) {
                int jw = jb + jc + 16 + ljw;
                rw0 = *(const float4*)&fc1w[(2*jw  )*KD + k0 + lcw];
                rw1 = *(const float4*)&fc1w[(2*jw+1)*KD + k0 + lcw];
            }
        }
        #pragma unroll
        for (int kk = 0; kk < 16; kk++) {
            float4 v4 = *(const float4*)&Vt [kk][ty*4];
            float4 x4 = *(const float4*)&VXt[kk][ty*4];
            float4 y4 = *(const float4*)&VYt[kk][ty*4];
            float2 w0 = *(const float2*)&W0t[kk][tx*2];
            float2 w1 = *(const float2*)&W1t[kk][tx*2];
            float vv[4] = {v4.x,v4.y,v4.z,v4.w};
            float xx[4] = {x4.x,x4.y,x4.z,x4.w};
            float yy[4] = {y4.x,y4.y,y4.z,y4.w};
            float a0[2] = {w0.x,w0.y};
            float a1[2] = {w1.x,w1.y};
            #pragma unroll
            for (int i = 0; i < 4; i++)
                #pragma unroll
                for (int j = 0; j < 2; j++) {
                    s0[i][j] = fmaf(vv[i], a0[j], s0[i][j]);
                    s1[i][j] = fmaf(vv[i], a1[j], s1[i][j]);
                    su[i][j] = fmaf(xx[i], a0[j], fmaf(yy[i], a1[j], su[i][j]));
                }
        }
        __syncthreads();
    }
    // RED.ADD into the single S plane
    float* S = d_acc + OFF_S;
    #pragma unroll
    for (int i = 0; i < 4; i++) {
        int bt = bt0 + ty*4 + i;
        int k  = k0 + tx*2;
        #pragma unroll
        for (int j = 0; j < 2; j++) {
            atomicAdd(&S[(0*BT + bt)*KD + k + j], s0[i][j]);
            atomicAdd(&S[(1*BT + bt)*KD + k + j], s1[i][j]);
            atomicAdd(&S[(2*BT + bt)*KD + k + j], su[i][j]);
        }
    }
}

// ---------------------------------------------------------------------------
// stage2 (PDL secondary, RED.ADD out, fused cvec): C (1024 x 768), K = 512.
//   A rows   (by 0..11):  A = S,   B = W2_top, split-K=8 (64 k/plane)
//   base rows(by 12..15): A = pos, B = W2_bot, split-K=2 (256 k, bz<2)
// Base blocks: mainloop is INDEPENDENT of stage1 -> runs concurrently;
// gridsync only before REDs (stage1's S2 zero must be done).
// A blocks: B-chunk prefetch pre-sync; gridsync before touching S.
// grid=(12, 16, 8), block=128, microtile 8x4.
// ---------------------------------------------------------------------------
__global__ void stage2_kernel(const float* __restrict__ fcoutw,
                              const float* __restrict__ pos,
                              const float* __restrict__ fc1b,
                              const float* __restrict__ fcoutb) {
    __shared__ float At[16][64];
    __shared__ float Bt[16][64];
    __shared__ float fb[16];
    int bx = blockIdx.x;           // n tile
    int by = blockIdx.y;           // m tile
    int bz = blockIdx.z;           // k split
    bool isBase = (by >= 12);
    if (isBase && bz >= 2) return;            // base rows only in planes 0,1
    bool doCvec = (by == 0);
    const float* Ap = isBase ? (pos + (by-12)*64*KD) : (d_acc + OFF_S + by*64*KD);
    const float* Bp = fcoutw + (isBase ? KD*DOUT : 0) + bx*64;
    int t  = threadIdx.x;
    int tx = t & 15;    // 4 cols
    int ty = t >> 4;    // 8 rows
    float acc[8][4];
    #pragma unroll
    for (int i = 0; i < 8; i++)
        #pragma unroll
        for (int j = 0; j < 4; j++) acc[i][j] = 0.f;
    float accC[4] = {0.f, 0.f, 0.f, 0.f};

    int arow = t >> 1;          // 0..63
    int koff = (t & 1) * 8;
    int bk   = t >> 4;          // 0..7 (and +8)
    int bn   = (t & 15) * 4;

    int kbeg = isBase ? bz*256 : bz*64;
    int kend = kbeg + (isBase ? 256 : 64);
    float4 ra0, ra1, rb0, rb1;
    rb0 = *(const float4*)&Bp[(kbeg+bk  )*DOUT + bn];
    rb1 = *(const float4*)&Bp[(kbeg+bk+8)*DOUT + bn];
    if (isBase) {
        ra0 = *(const float4*)&Ap[arow*KD + kbeg + koff];
        ra1 = *(const float4*)&Ap[arow*KD + kbeg + koff + 4];
    } else {
#if __CUDA_ARCH__ >= 900
        cudaGridDependencySynchronize();      // S must be complete
#endif
        ra0 = *(const float4*)&Ap[arow*KD + kbeg + koff];
        ra1 = *(const float4*)&Ap[arow*KD + kbeg + koff + 4];
    }

    for (int kc = kbeg; kc < kend; kc += 16) {
        At[koff+0][arow] = ra0.x; At[koff+1][arow] = ra0.y;
        At[koff+2][arow] = ra0.z; At[koff+3][arow] = ra0.w;
        At[koff+4][arow] = ra1.x; At[koff+5][arow] = ra1.y;
        At[koff+6][arow] = ra1.z; At[koff+7][arow] = ra1.w;
        *(float4*)&Bt[bk  ][bn] = rb0;
        *(float4*)&Bt[bk+8][bn] = rb1;
        if (doCvec && t < 16) fb[t] = fc1b[kc + t];
        __syncthreads();
        if (kc + 16 < kend) {            // prefetch next chunk
            ra0 = *(const float4*)&Ap[arow*KD + kc + 16 + koff];
            ra1 = *(const float4*)&Ap[arow*KD + kc + 16 + koff + 4];
            rb0 = *(const float4*)&Bp[(kc+16+bk  )*DOUT + bn];
            rb1 = *(const float4*)&Bp[(kc+16+bk+8)*DOUT + bn];
        }
        #pragma unroll
        for (int kk = 0; kk < 16; kk++) {
            float4 b4 = *(const float4*)&Bt[kk][tx*4];
            float4 aA = *(const float4*)&At[kk][ty*8];
            float4 aB = *(const float4*)&At[kk][ty*8 + 4];
            float av[8] = {aA.x,aA.y,aA.z,aA.w,aB.x,aB.y,aB.z,aB.w};
            float bv[4] = {b4.x,b4.y,b4.z,b4.w};
            if (doCvec) {
                float fbv = fb[kk];
                #pragma unroll
                for (int j = 0; j < 4; j++)
                    accC[j] = fmaf(fbv, bv[j], accC[j]);
            }
            #pragma unroll
            for (int i = 0; i < 8; i++)
                #pragma unroll
                for (int j = 0; j < 4; j++)
                    acc[i][j] = fmaf(av[i], bv[j], acc[i][j]);
        }
        __syncthreads();
    }

#if __CUDA_ARCH__ >= 900
    if (isBase) cudaGridDependencySynchronize();  // stage1's S2 zero done
#endif

    int row0 = by*64 + ty*8;
    int col  = bx*64 + tx*4;
    if (doCvec && ty == 0) {
        if (bz == 0) {
            accC[0] += fcoutb[col];   accC[1] += fcoutb[col+1];
            accC[2] += fcoutb[col+2]; accC[3] += fcoutb[col+3];
        }
        float* cvp = d_acc + OFF_CV;
        #pragma unroll
        for (int j = 0; j < 4; j++)
            atomicAdd(&cvp[col + j], accC[j]);
    }
    float* S2 = d_acc + OFF_S2;
    #pragma unroll
    for (int i = 0; i < 8; i++)
        #pragma unroll
        for (int j = 0; j < 4; j++)
            atomicAdd(&S2[(row0+i)*DOUT + col + j], acc[i][j]);
}

// ---------------------------------------------------------------------------
// epilogue: out[bt,m,o] = VX*A0 + VY*A1 - V*AU + base[m,o] + cvec[o]
// Single-plane reads. 384 threads: warps 0-5 -> bt {0,1}, warps 6-11 -> bt
// {2,3}. Base tile (16 m, +cvec) in 49 KB smem; A in regs; simple store loop.
// Tail: zero the S region for the NEXT replay. grid=(64 bt-quads, 16 m-tiles).
// ---------------------------------------------------------------------------
#define EPI_BT 4
#define EPI_M  16
#define EPI_THREADS 384
__global__ __launch_bounds__(EPI_THREADS, 3)
void epilogue_kernel(const float* __restrict__ coords,
                     const float* __restrict__ vis,
                     float* __restrict__ out) {
    extern __shared__ float4 sm[];
    float4* sBase = sm;                    // [EPI_M][192]
    float4* sVp   = sm + EPI_M*NF4;        // [EPI_M][EPI_BT] (vx, vy, v, 0)

    int bt0 = blockIdx.x * EPI_BT;
    int m0  = blockIdx.y * EPI_M;
    int t   = threadIdx.x;     // 0..383
    int w   = t >> 5, l = t & 31;
    int tcol = (w % 6)*32 + l;   // 0..191
    int bth  = w / 6;            // 0 or 1 (bt half)

    const float4* S2 = (const float4*)(d_acc + OFF_S2);

    float4 cv = ((const float4*)(d_acc + OFF_CV))[tcol];

    #pragma unroll
    for (int k = 0; k < EPI_M/2; k++) {
        int mm = bth*(EPI_M/2) + k;
        float4 u = S2[(768 + m0 + mm)*NF4 + tcol];
        sBase[mm*NF4 + tcol] = make_float4(u.x+cv.x, u.y+cv.y, u.z+cv.z, u.w+cv.w);
    }
    float4 a0[2], a1[2], au[2];
    #pragma unroll
    for (int i = 0; i < 2; i++) {
        int bt = bt0 + bth*2 + i;
        a0[i] = S2[(0*BT + bt)*NF4 + tcol];
        a1[i] = S2[(1*BT + bt)*NF4 + tcol];
        au[i] = S2[(2*BT + bt)*NF4 + tcol];
    }
    if (t < EPI_M*EPI_BT) {
        int mm = t >> 2, bi = t & 3;
        int bt = bt0 + bi;
        int b = bt >> 6, tt = bt & 63;
        int ci = (b*Mm + (m0+mm))*Tt + tt;
        float x = coords[2*ci], y = coords[2*ci+1], v = vis[ci];
        if (is_nan_bits(x)) { v = 0.f; x = 0.f; }
        if (is_nan_bits(y)) { y = 0.f; }
        sVp[mm*EPI_BT + bi] = make_float4(x*v, y*v, v, 0.f);
    }

    // distributed zero of S region for next replay (1024 blocks x 384 thr)
    {
        int bid = blockIdx.y*64 + blockIdx.x;               // 0..1023
        float4* z = (float4*)(d_acc + OFF_S);
        int idx = bid*384 + t;
        const int SF4 = PSZ/4;                              // 98304
        if (idx < SF4) z[idx] = make_float4(0.f,0.f,0.f,0.f);
    }
    __syncthreads();

    #pragma unroll 4
    for (int mm = 0; mm < EPI_M; mm++) {
        float4 bv = sBase[mm*NF4 + tcol];
        int m = m0 + mm;
        #pragma unroll
        for (int i = 0; i < 2; i++) {
            float4 vp = sVp[mm*EPI_BT + bth*2 + i];
            float4 o4;
            o4.x = fmaf(vp.x, a0[i].x, fmaf(vp.y, a1[i].x, fmaf(-vp.z, au[i].x, bv.x)));
            o4.y = fmaf(vp.x, a0[i].y, fmaf(vp.y, a1[i].y, fmaf(-vp.z, au[i].y, bv.y)));
            o4.z = fmaf(vp.x, a0[i].z, fmaf(vp.y, a1[i].z, fmaf(-vp.z, au[i].z, bv.z)));
            o4.w = fmaf(vp.x, a0[i].w, fmaf(vp.y, a1[i].w, fmaf(-vp.z, au[i].w, bv.w)));
            ((float4*)out)[((bt0 + bth*2 + i)*Mm + m)*NF4 + tcol] = o4;
        }
    }
}

// ---------------------------------------------------------------------------
extern "C" void kernel_launch(void* const* d_in, const int* in_sizes, int n_in,
                              void* d_out, int out_size) {
    const float* coords = (const float*)d_in[0];
    const float* vis    = (const float*)d_in[1];
    const float* pos    = (const float*)d_in[2];
    const float* fc1w   = (const float*)d_in[3];
    const float* fc1b   = (const float*)d_in[4];
    const float* fcoutw = (const float*)d_in[5];
    const float* fcoutb = (const float*)d_in[6];
    float* out = (float*)d_out;

    static int smem_set = 0;
    int epi_smem = EPI_M*NF4*16 + EPI_M*EPI_BT*16;   // 50,176 B
    if (!smem_set) {
        cudaFuncSetAttribute(epilogue_kernel,
                             cudaFuncAttributeMaxDynamicSharedMemorySize, epi_smem);
        smem_set = 1;
    }

    stage1_kernel<<<dim3(4,16,JSPLIT), 256>>>(coords, vis, fc1w);

    // stage2 as PDL secondary: launches while stage1 runs; base blocks
    // compute concurrently, gridsync guards all d_acc dependencies.
    {
        cudaLaunchConfig_t cfg = {};
        cfg.gridDim  = dim3(12,16,KSPLIT);
        cfg.blockDim = dim3(128,1,1);
        cfg.dynamicSmemBytes = 0;
        cfg.stream = 0;
        cudaLaunchAttribute attr[1];
        attr[0].id = cudaLaunchAttributeProgrammaticStreamSerialization;
        attr[0].val.programmaticStreamSerializationAllowed = 1;
        cfg.attrs = attr;
        cfg.numAttrs = 1;
        cudaLaunchKernelEx(&cfg, stage2_kernel, fcoutw, pos, fc1b, fcoutb);
    }

    epilogue_kernel<<<dim3(BT/EPI_BT, Mm/EPI_M), EPI_THREADS, epi_smem>>>(coords, vis, out);
}